// round 10
// baseline (speedup 1.0000x reference)
#include <cuda_runtime.h>
#include <stdint.h>

#define SEQ    2048
#define BITS   256
#define HEADS  8
#define NBPN   12
#define MAXD   8
#define NT     1024
#define GRID_MAIN 152

// Scratch (device globals -- no allocation allowed)
__device__ uint32_t       g_tok[SEQ * 8];          // packed token bits, 32B/row
__device__ unsigned short g_AkE[SEQ * 8];          // EXPANDED ak per (row,head)
__device__ uint32_t       g_AqU[SEQ * 8];          // expand(h<<12 | aq | ar8)
__device__ uint32_t       g_tabBits[HEADS * 128];  // bit-packed table, 4KB
__device__ int            g_ArX[(MAXD + 1) * HEADS]; // expand(ar_d)^expand(ar_8)

// expand: 12-bit table index -> (wordByteOffset<<7)|(bitIndex), a pure bit
// permutation (valid because q/k/r address bits are disjoint -> + == |)
__device__ __forceinline__ uint32_t expand_idx(uint32_t x) {
    return ((x & ~31u) << 2) | (x & 31u);
}

// ---------------------------------------------------------------------------
// Precompute
// ---------------------------------------------------------------------------
__global__ void pre_kernel(const int* __restrict__ tokens,
                           const int* __restrict__ head_idx,
                           const float* __restrict__ table) {
    int tid = blockIdx.x * blockDim.x + threadIdx.x;
    int lane = tid & 31;

    if (tid < HEADS * 4096) {
        uint32_t w = __ballot_sync(0xFFFFFFFFu, table[tid] > 0.5f);
        if (lane == 0) g_tabBits[tid >> 5] = w;
    }

    if (tid < (MAXD + 1) * HEADS) {
        int d = tid / HEADS, h = tid % HEADS;
        uint32_t ard = 0, ar8 = 0;
        for (int k = 0; k < NBPN; k++) {
            int idx = head_idx[h * NBPN + k];
            if (idx >= 2 * BITS) {
                int p = idx - 2 * BITS;
                if (p > 3) p = 3;
                ard |= (uint32_t)((d    >> p) & 1) << k;
                ar8 |= (uint32_t)((MAXD >> p) & 1) << k;
            }
        }
        g_ArX[tid] = (int)(expand_idx(ard) ^ expand_idx(ar8));
    }

    int row = tid >> 5;
    if (row < SEQ) {
        uint32_t w[8];
        #pragma unroll
        for (int q = 0; q < 8; q++) {
            int v = tokens[row * BITS + q * 32 + lane];
            w[q] = __ballot_sync(0xFFFFFFFFu, v & 1);
        }
        if (lane < 8) {
            g_tok[row * 8 + lane] = w[lane];
            int h = lane;
            uint32_t aq = 0, ak = 0, ar8 = 0;
            for (int k = 0; k < NBPN; k++) {
                int idx = head_idx[h * NBPN + k];
                if (idx < BITS) {
                    aq |= ((w[idx >> 5] >> (idx & 31)) & 1u) << k;
                } else if (idx < 2 * BITS) {
                    int i2 = idx - BITS;
                    ak |= ((w[i2 >> 5] >> (i2 & 31)) & 1u) << k;
                } else {
                    int p = idx - 2 * BITS;
                    if (p > 3) p = 3;
                    ar8 |= (uint32_t)((MAXD >> p) & 1) << k;
                }
            }
            g_AkE[row * 8 + h] = (unsigned short)expand_idx(ak);
            g_AqU[row * 8 + h] = expand_idx(((uint32_t)h << 12) | aq | ar8);
        }
    }
}

// ---------------------------------------------------------------------------
// Main: persistent CTAs, TWO WARPS PER ROW, bank-private replicated bit-table,
// additive expanded addressing, diagonal peeled, unroll-4 mainloop,
// IMAD-based argmax key, SMSP-balanced row permutation.
// ---------------------------------------------------------------------------
__global__ __launch_bounds__(NT, 1)
void main_kernel(float* __restrict__ out) {
    extern __shared__ unsigned char smem[];
    // sRep at offset 0: word w, replica L at byte w*128 + L*4
    uint4*    sAk4   = (uint4*)(smem + 131072);           // 32768 B (expanded Ak)
    uint4*    sTokLo = (uint4*)(smem + 163840);           // 32768 B
    uint4*    sTokHi = (uint4*)(smem + 196608);           // 32768 B
    int*      sArX   = (int*)(smem + 229376);             // 72 ints
    uint32_t* sRed   = (uint32_t*)(smem + 229664);        // 32 warps x 9

    const int tid = threadIdx.x;
    const int lane = tid & 31, wid = tid >> 5;

    // Stage working set
    {
        uint32_t val = g_tabBits[tid];
        uint32_t* sRep = (uint32_t*)smem;
        #pragma unroll
        for (int r = 0; r < 32; r++) {
            int L = (r + lane) & 31;                 // staggered, conflict-free
            sRep[tid * 32 + L] = val;
        }
        const uint4* g2 = (const uint4*)g_AkE;
        for (int x = tid; x < 2048; x += NT) sAk4[x] = g2[x];
        const uint4* g3 = (const uint4*)g_tok;
        for (int x = tid; x < 4096; x += NT) {
            uint4 v = g3[x];
            if (x & 1) sTokHi[x >> 1] = v; else sTokLo[x >> 1] = v;
        }
        if (tid < (MAXD + 1) * HEADS) sArX[tid] = g_ArX[tid];
    }
    __syncthreads();

    const int pair = wid >> 1, sub = wid & 1;
    // SMSP balance: even pairs run on SMSP{0,1}, odd on {2,3}. Permute the
    // row-block so both groups carry equal total row length.
    const int pb = (pair >> 1) & 1;
    const int rowblk = pair + ((pair & 1) ? -pb : pb);   // bijection on 0..15
    const int bx = (int)blockIdx.x;
    const int i = rowblk * GRID_MAIN + ((rowblk & 1) ? (GRID_MAIN - 1 - bx) : bx);
    const bool active = (i < SEQ);

    uint32_t a[8] = {0, 0, 0, 0, 0, 0, 0, 0};
    int kmax = -1;
    const uint32_t laneOff = (uint32_t)lane << 2;

    if (active) {
        uint32_t u[8];
        {
            const uint4* gu = (const uint4*)(g_AqU + i * 8);
            uint4 u03 = gu[0], u47 = gu[1];
            u[0] = u03.x; u[1] = u03.y; u[2] = u03.z; u[3] = u03.w;
            u[4] = u47.x; u[5] = u47.y; u[6] = u47.z; u[7] = u47.w;
        }

        // main loop: j <= i-8 (rel part is exactly ar8 here; no fixups)
        int jj = 2047 - (lane + 32 * sub);     // argmax tiebreak key countdown
        #pragma unroll 4
        for (int j = lane + 32 * sub; j + MAXD <= i; j += 64, jj -= 64) {
            uint4 akv = sAk4[j];
            uint32_t A0 = u[0] + (akv.x & 0xFFFFu);
            uint32_t A1 = u[1] + (akv.x >> 16);
            uint32_t A2 = u[2] + (akv.y & 0xFFFFu);
            uint32_t A3 = u[3] + (akv.y >> 16);
            uint32_t A4 = u[4] + (akv.z & 0xFFFFu);
            uint32_t A5 = u[5] + (akv.z >> 16);
            uint32_t A6 = u[6] + (akv.w & 0xFFFFu);
            uint32_t A7 = u[7] + (akv.w >> 16);

            uint32_t w0 = *(const uint32_t*)(smem + ((A0 & 0xFFFFFF80u) | laneOff));
            uint32_t w1 = *(const uint32_t*)(smem + ((A1 & 0xFFFFFF80u) | laneOff));
            uint32_t w2 = *(const uint32_t*)(smem + ((A2 & 0xFFFFFF80u) | laneOff));
            uint32_t w3 = *(const uint32_t*)(smem + ((A3 & 0xFFFFFF80u) | laneOff));
            uint32_t w4 = *(const uint32_t*)(smem + ((A4 & 0xFFFFFF80u) | laneOff));
            uint32_t w5 = *(const uint32_t*)(smem + ((A5 & 0xFFFFFF80u) | laneOff));
            uint32_t w6 = *(const uint32_t*)(smem + ((A6 & 0xFFFFFF80u) | laneOff));
            uint32_t w7 = *(const uint32_t*)(smem + ((A7 & 0xFFFFFF80u) | laneOff));

            int v = (int)((w0 >> (A0 & 31u)) & 1u) + (int)((w1 >> (A1 & 31u)) & 1u)
                  + (int)((w2 >> (A2 & 31u)) & 1u) + (int)((w3 >> (A3 & 31u)) & 1u)
                  + (int)((w4 >> (A4 & 31u)) & 1u) + (int)((w5 >> (A5 & 31u)) & 1u)
                  + (int)((w6 >> (A6 & 31u)) & 1u) + (int)((w7 >> (A7 & 31u)) & 1u);

            if (v >= HEADS / 2) {      // divergent but cheap: plain XOR path
                uint4 t0 = sTokLo[j];
                uint4 t1 = sTokHi[j];
                a[0] ^= t0.x; a[1] ^= t0.y; a[2] ^= t0.z; a[3] ^= t0.w;
                a[4] ^= t1.x; a[5] ^= t1.y; a[6] ^= t1.z; a[7] ^= t1.w;
            }
            kmax = max(kmax, v * 4096 + jj);   // IMAD + IMNMX (fma pipe)
        }

        // diagonal tail: d = 0..7, lane d handles j = i-d (sub 0 warp only)
        if (sub == 0 && lane < MAXD && lane <= i) {
            int jt = i - lane;
            const unsigned short* s = (const unsigned short*)sAk4 + jt * 8;
            const int* ax = sArX + lane * 8;
            int v = 0;
            #pragma unroll
            for (int h = 0; h < 8; h++) {
                uint32_t A = (u[h] ^ (uint32_t)ax[h]) + (uint32_t)s[h];
                uint32_t w = *(const uint32_t*)(smem + ((A & 0xFFFFFF80u) | laneOff));
                v += (int)((w >> (A & 31u)) & 1u);
            }
            if (v >= HEADS / 2) {
                uint4 t0 = sTokLo[jt];
                uint4 t1 = sTokHi[jt];
                a[0] ^= t0.x; a[1] ^= t0.y; a[2] ^= t0.z; a[3] ^= t0.w;
                a[4] ^= t1.x; a[5] ^= t1.y; a[6] ^= t1.z; a[7] ^= t1.w;
            }
            kmax = max(kmax, v * 4096 + (2047 - jt));
        }

        // warp butterfly
        #pragma unroll
        for (int s = 16; s; s >>= 1) {
            #pragma unroll
            for (int q = 0; q < 8; q++)
                a[q] ^= __shfl_xor_sync(0xFFFFFFFFu, a[q], s);
            kmax = max(kmax, __shfl_xor_sync(0xFFFFFFFFu, kmax, s));
        }

        // odd warp parks its partial for its even partner
        if (sub == 1 && lane < 9) {
            uint32_t v = (lane < 8) ? a[lane] : (uint32_t)kmax;
            sRed[wid * 9 + lane] = v;
        }
    }

    __syncthreads();   // single block sync

    if (active && sub == 0) {
        const uint32_t* p = sRed + (wid + 1) * 9;
        #pragma unroll
        for (int q = 0; q < 8; q++) a[q] ^= p[q];
        kmax = max(kmax, (int)p[8]);

        int widx = lane >> 2;
        uint32_t w;
        if ((kmax >> 12) >= HEADS / 2) {          // any attended -> parity
            w = a[0];
            if (widx == 1) w = a[1];
            if (widx == 2) w = a[2];
            if (widx == 3) w = a[3];
            if (widx == 4) w = a[4];
            if (widx == 5) w = a[5];
            if (widx == 6) w = a[6];
            if (widx == 7) w = a[7];
        } else {                                   // fallback: argmax row
            int aj = 2047 - (kmax & 4095);
            const uint32_t* lo = (const uint32_t*)sTokLo;
            const uint32_t* hi = (const uint32_t*)sTokHi;
            w = (widx < 4) ? lo[aj * 4 + widx] : hi[aj * 4 + (widx - 4)];
        }
        int sh = (lane & 3) * 8;
        float4* o = (float4*)(out + i * BITS + lane * 8);
        o[0] = make_float4((float)((w >> (sh + 0)) & 1u), (float)((w >> (sh + 1)) & 1u),
                           (float)((w >> (sh + 2)) & 1u), (float)((w >> (sh + 3)) & 1u));
        o[1] = make_float4((float)((w >> (sh + 4)) & 1u), (float)((w >> (sh + 5)) & 1u),
                           (float)((w >> (sh + 6)) & 1u), (float)((w >> (sh + 7)) & 1u));
    }
}

extern "C" void kernel_launch(void* const* d_in, const int* in_sizes, int n_in,
                              void* d_out, int out_size) {
    const int*   tokens   = (const int*)d_in[0];
    const int*   head_idx = (const int*)d_in[1];
    const float* table    = (const float*)d_in[2];
    float*       out      = (float*)d_out;

    const int SMEM_BYTES = 229664 + 32 * 9 * 4;   // 230816 B
    cudaFuncSetAttribute(main_kernel,
                         cudaFuncAttributeMaxDynamicSharedMemorySize, SMEM_BYTES);

    pre_kernel<<<(SEQ * 32 + 255) / 256, 256>>>(tokens, head_idx, table);
    main_kernel<<<GRID_MAIN, NT, SMEM_BYTES>>>(out);
}

// round 12
// speedup vs baseline: 1.0137x; 1.0137x over previous
#include <cuda_runtime.h>
#include <stdint.h>

#define SEQ    2048
#define BITS   256
#define HEADS  8
#define NBPN   12
#define MAXD   8
#define NT     1024
#define GRID_MAIN 152

// Scratch (device globals -- no allocation allowed)
__device__ uint32_t       g_tok[SEQ * 8];          // packed token bits, 32B/row
__device__ unsigned short g_AkE[SEQ * 8];          // EXPANDED ak per (row,head)
__device__ uint32_t       g_AqU[SEQ * 8];          // expand(h<<12 | aq | ar8)
__device__ uint32_t       g_tabBits[HEADS * 128];  // bit-packed table, 4KB
__device__ int            g_ArX[(MAXD + 1) * HEADS]; // expand(ar_d)^expand(ar_8)

// expand: 12-bit table index -> (wordByteOffset<<7)|(bitIndex), a pure bit
// permutation (valid because q/k/r address bits are disjoint -> + == |)
__device__ __forceinline__ uint32_t expand_idx(uint32_t x) {
    return ((x & ~31u) << 2) | (x & 31u);
}

// ---------------------------------------------------------------------------
// Precompute
// ---------------------------------------------------------------------------
__global__ void pre_kernel(const int* __restrict__ tokens,
                           const int* __restrict__ head_idx,
                           const float* __restrict__ table) {
    int tid = blockIdx.x * blockDim.x + threadIdx.x;
    int lane = tid & 31;

    if (tid < HEADS * 4096) {
        uint32_t w = __ballot_sync(0xFFFFFFFFu, table[tid] > 0.5f);
        if (lane == 0) g_tabBits[tid >> 5] = w;
    }

    if (tid < (MAXD + 1) * HEADS) {
        int d = tid / HEADS, h = tid % HEADS;
        uint32_t ard = 0, ar8 = 0;
        for (int k = 0; k < NBPN; k++) {
            int idx = head_idx[h * NBPN + k];
            if (idx >= 2 * BITS) {
                int p = idx - 2 * BITS;
                if (p > 3) p = 3;
                ard |= (uint32_t)((d    >> p) & 1) << k;
                ar8 |= (uint32_t)((MAXD >> p) & 1) << k;
            }
        }
        g_ArX[tid] = (int)(expand_idx(ard) ^ expand_idx(ar8));
    }

    int row = tid >> 5;
    if (row < SEQ) {
        uint32_t w[8];
        #pragma unroll
        for (int q = 0; q < 8; q++) {
            int v = tokens[row * BITS + q * 32 + lane];
            w[q] = __ballot_sync(0xFFFFFFFFu, v & 1);
        }
        if (lane < 8) {
            g_tok[row * 8 + lane] = w[lane];
            int h = lane;
            uint32_t aq = 0, ak = 0, ar8 = 0;
            for (int k = 0; k < NBPN; k++) {
                int idx = head_idx[h * NBPN + k];
                if (idx < BITS) {
                    aq |= ((w[idx >> 5] >> (idx & 31)) & 1u) << k;
                } else if (idx < 2 * BITS) {
                    int i2 = idx - BITS;
                    ak |= ((w[i2 >> 5] >> (i2 & 31)) & 1u) << k;
                } else {
                    int p = idx - 2 * BITS;
                    if (p > 3) p = 3;
                    ar8 |= (uint32_t)((MAXD >> p) & 1) << k;
                }
            }
            g_AkE[row * 8 + h] = (unsigned short)expand_idx(ak);
            g_AqU[row * 8 + h] = expand_idx(((uint32_t)h << 12) | aq | ar8);
        }
    }
}

// ---------------------------------------------------------------------------
// Main: persistent CTAs, TWO WARPS PER ROW, bank-private replicated bit-table,
// additive expanded addressing, diagonal peeled, BRANCHLESS token XOR (LOP3
// a^=t&m) + software-pipelined akv prefetch: three independent LDS streams.
// ---------------------------------------------------------------------------
__global__ __launch_bounds__(NT, 1)
void main_kernel(float* __restrict__ out) {
    extern __shared__ unsigned char smem[];
    // sRep at offset 0: word w, replica L at byte w*128 + L*4
    uint4*    sAk4   = (uint4*)(smem + 131072);           // 32768 B (expanded Ak)
    uint4*    sTokLo = (uint4*)(smem + 163840);           // 32768 B
    uint4*    sTokHi = (uint4*)(smem + 196608);           // 32768 B
    int*      sArX   = (int*)(smem + 229376);             // 72 ints
    uint32_t* sRed   = (uint32_t*)(smem + 229664);        // 32 warps x 9

    const int tid = threadIdx.x;
    const int lane = tid & 31, wid = tid >> 5;

    // Stage working set
    {
        uint32_t val = g_tabBits[tid];
        uint32_t* sRep = (uint32_t*)smem;
        #pragma unroll
        for (int r = 0; r < 32; r++) {
            int L = (r + lane) & 31;                 // staggered, conflict-free
            sRep[tid * 32 + L] = val;
        }
        const uint4* g2 = (const uint4*)g_AkE;
        for (int x = tid; x < 2048; x += NT) sAk4[x] = g2[x];
        const uint4* g3 = (const uint4*)g_tok;
        for (int x = tid; x < 4096; x += NT) {
            uint4 v = g3[x];
            if (x & 1) sTokHi[x >> 1] = v; else sTokLo[x >> 1] = v;
        }
        if (tid < (MAXD + 1) * HEADS) sArX[tid] = g_ArX[tid];
    }
    __syncthreads();

    const int pair = wid >> 1, sub = wid & 1;
    // SMSP balance: permute row-blocks so both SMSP groups carry equal work.
    const int pb = (pair >> 1) & 1;
    const int rowblk = pair + ((pair & 1) ? -pb : pb);   // bijection on 0..15
    const int bx = (int)blockIdx.x;
    const int i = rowblk * GRID_MAIN + ((rowblk & 1) ? (GRID_MAIN - 1 - bx) : bx);
    const bool active = (i < SEQ);

    uint32_t a[8] = {0, 0, 0, 0, 0, 0, 0, 0};
    int kmax = -1;
    const uint32_t laneOff = (uint32_t)lane << 2;

    if (active) {
        uint32_t u[8];
        {
            const uint4* gu = (const uint4*)(g_AqU + i * 8);
            uint4 u03 = gu[0], u47 = gu[1];
            u[0] = u03.x; u[1] = u03.y; u[2] = u03.z; u[3] = u03.w;
            u[4] = u47.x; u[5] = u47.y; u[6] = u47.z; u[7] = u47.w;
        }

        // main loop: j <= i-8 (rel part is exactly ar8; no fixups).
        int j = lane + 32 * sub;
        const int jend = i - MAXD;
        int jj = 2047 - j;
        if (j <= jend) {
            uint4 akv = sAk4[j];                      // primed
            #pragma unroll 2
            for (; j <= jend; j += 64, jj -= 64) {
                // prefetch next akv (clamped dummy read at the tail)
                uint4 akn = sAk4[min(j + 64, jend)];
                // token words: unconditional, independent of gather chain
                uint4 t0 = sTokLo[j];
                uint4 t1 = sTokHi[j];

                uint32_t A0 = u[0] + (akv.x & 0xFFFFu);
                uint32_t A1 = u[1] + (akv.x >> 16);
                uint32_t A2 = u[2] + (akv.y & 0xFFFFu);
                uint32_t A3 = u[3] + (akv.y >> 16);
                uint32_t A4 = u[4] + (akv.z & 0xFFFFu);
                uint32_t A5 = u[5] + (akv.z >> 16);
                uint32_t A6 = u[6] + (akv.w & 0xFFFFu);
                uint32_t A7 = u[7] + (akv.w >> 16);

                uint32_t w0 = *(const uint32_t*)(smem + ((A0 & 0xFFFFFF80u) | laneOff));
                uint32_t w1 = *(const uint32_t*)(smem + ((A1 & 0xFFFFFF80u) | laneOff));
                uint32_t w2 = *(const uint32_t*)(smem + ((A2 & 0xFFFFFF80u) | laneOff));
                uint32_t w3 = *(const uint32_t*)(smem + ((A3 & 0xFFFFFF80u) | laneOff));
                uint32_t w4 = *(const uint32_t*)(smem + ((A4 & 0xFFFFFF80u) | laneOff));
                uint32_t w5 = *(const uint32_t*)(smem + ((A5 & 0xFFFFFF80u) | laneOff));
                uint32_t w6 = *(const uint32_t*)(smem + ((A6 & 0xFFFFFF80u) | laneOff));
                uint32_t w7 = *(const uint32_t*)(smem + ((A7 & 0xFFFFFF80u) | laneOff));

                int v = (int)((w0 >> (A0 & 31u)) & 1u) + (int)((w1 >> (A1 & 31u)) & 1u)
                      + (int)((w2 >> (A2 & 31u)) & 1u) + (int)((w3 >> (A3 & 31u)) & 1u)
                      + (int)((w4 >> (A4 & 31u)) & 1u) + (int)((w5 >> (A5 & 31u)) & 1u)
                      + (int)((w6 >> (A6 & 31u)) & 1u) + (int)((w7 >> (A7 & 31u)) & 1u);

                // branchless: a ^= t & m is one LOP3 per word
                uint32_t m = (uint32_t)(-(int)(v >= HEADS / 2));
                a[0] ^= t0.x & m; a[1] ^= t0.y & m; a[2] ^= t0.z & m; a[3] ^= t0.w & m;
                a[4] ^= t1.x & m; a[5] ^= t1.y & m; a[6] ^= t1.z & m; a[7] ^= t1.w & m;

                kmax = max(kmax, v * 4096 + jj);   // IMAD + IMNMX (fma pipe)
                akv = akn;
            }
        }

        // diagonal tail: d = 0..7, lane d handles j = i-d (sub 0 warp only)
        if (sub == 0 && lane < MAXD && lane <= i) {
            int jt = i - lane;
            const unsigned short* s = (const unsigned short*)sAk4 + jt * 8;
            const int* ax = sArX + lane * 8;
            int v = 0;
            #pragma unroll
            for (int h = 0; h < 8; h++) {
                uint32_t A = (u[h] ^ (uint32_t)ax[h]) + (uint32_t)s[h];
                uint32_t w = *(const uint32_t*)(smem + ((A & 0xFFFFFF80u) | laneOff));
                v += (int)((w >> (A & 31u)) & 1u);
            }
            uint32_t m = (uint32_t)(-(int)(v >= HEADS / 2));
            uint4 t0 = sTokLo[jt];
            uint4 t1 = sTokHi[jt];
            a[0] ^= t0.x & m; a[1] ^= t0.y & m; a[2] ^= t0.z & m; a[3] ^= t0.w & m;
            a[4] ^= t1.x & m; a[5] ^= t1.y & m; a[6] ^= t1.z & m; a[7] ^= t1.w & m;
            kmax = max(kmax, v * 4096 + (2047 - jt));
        }

        // warp butterfly
        #pragma unroll
        for (int s = 16; s; s >>= 1) {
            #pragma unroll
            for (int q = 0; q < 8; q++)
                a[q] ^= __shfl_xor_sync(0xFFFFFFFFu, a[q], s);
            kmax = max(kmax, __shfl_xor_sync(0xFFFFFFFFu, kmax, s));
        }

        // odd warp parks its partial for its even partner
        if (sub == 1 && lane < 9) {
            uint32_t v = (lane < 8) ? a[lane] : (uint32_t)kmax;
            sRed[wid * 9 + lane] = v;
        }
    }

    __syncthreads();   // single block sync

    if (active && sub == 0) {
        const uint32_t* p = sRed + (wid + 1) * 9;
        #pragma unroll
        for (int q = 0; q < 8; q++) a[q] ^= p[q];
        kmax = max(kmax, (int)p[8]);

        int widx = lane >> 2;
        uint32_t w;
        if ((kmax >> 12) >= HEADS / 2) {          // any attended -> parity
            w = a[0];
            if (widx == 1) w = a[1];
            if (widx == 2) w = a[2];
            if (widx == 3) w = a[3];
            if (widx == 4) w = a[4];
            if (widx == 5) w = a[5];
            if (widx == 6) w = a[6];
            if (widx == 7) w = a[7];
        } else {                                   // fallback: argmax row
            int aj = 2047 - (kmax & 4095);
            const uint32_t* lo = (const uint32_t*)sTokLo;
            const uint32_t* hi = (const uint32_t*)sTokHi;
            w = (widx < 4) ? lo[aj * 4 + widx] : hi[aj * 4 + (widx - 4)];
        }
        int sh = (lane & 3) * 8;
        float4* o = (float4*)(out + i * BITS + lane * 8);
        o[0] = make_float4((float)((w >> (sh + 0)) & 1u), (float)((w >> (sh + 1)) & 1u),
                           (float)((w >> (sh + 2)) & 1u), (float)((w >> (sh + 3)) & 1u));
        o[1] = make_float4((float)((w >> (sh + 4)) & 1u), (float)((w >> (sh + 5)) & 1u),
                           (float)((w >> (sh + 6)) & 1u), (float)((w >> (sh + 7)) & 1u));
    }
}

extern "C" void kernel_launch(void* const* d_in, const int* in_sizes, int n_in,
                              void* d_out, int out_size) {
    const int*   tokens   = (const int*)d_in[0];
    const int*   head_idx = (const int*)d_in[1];
    const float* table    = (const float*)d_in[2];
    float*       out      = (float*)d_out;

    const int SMEM_BYTES = 229664 + 32 * 9 * 4;   // 230816 B
    cudaFuncSetAttribute(main_kernel,
                         cudaFuncAttributeMaxDynamicSharedMemorySize, SMEM_BYTES);

    pre_kernel<<<(SEQ * 32 + 255) / 256, 256>>>(tokens, head_idx, table);
    main_kernel<<<GRID_MAIN, NT, SMEM_BYTES>>>(out);
}

// round 13
// speedup vs baseline: 1.1235x; 1.1083x over previous
#include <cuda_runtime.h>
#include <stdint.h>

#define SEQ    2048
#define BITS   256
#define HEADS  8
#define NBPN   12
#define MAXD   8
#define NT     1024
#define GRID_MAIN 152

// Scratch (device globals -- no allocation allowed)
__device__ uint32_t       g_tok[SEQ * 8];          // packed token bits, 32B/row
__device__ unsigned short g_AkE[SEQ * 8];          // EXPANDED ak per (row,head)
__device__ uint32_t       g_AqU[SEQ * 8];          // expand(h<<12 | aq | ar8)
__device__ uint32_t       g_tabBits[HEADS * 128];  // bit-packed table, 4KB
__device__ unsigned int   g_bar = 0;               // monotonic ticket barrier

// expand: 12-bit table index -> (wordByteOffset<<7)|(bitIndex), a pure bit
// permutation (valid because q/k/r address bits are disjoint -> + == |)
__device__ __forceinline__ uint32_t expand_idx(uint32_t x) {
    return ((x & ~31u) << 2) | (x & 31u);
}

// ---------------------------------------------------------------------------
// ONE fused persistent kernel: Phase A distributes precompute across the 152
// co-resident CTAs, a global ticket barrier orders it, Phase B is the proven
// R12 main loop (bank-private replicated bit-table, additive expanded
// addressing, diagonal peel, branchless token XOR, akv prefetch).
// ---------------------------------------------------------------------------
__global__ __launch_bounds__(NT, 1)
void fused_kernel(const int* __restrict__ tokens,
                  const int* __restrict__ head_idx,
                  const float* __restrict__ table,
                  float* __restrict__ out) {
    extern __shared__ unsigned char smem[];
    // sRep at offset 0: word w, replica L at byte w*128 + L*4
    uint4*    sAk4   = (uint4*)(smem + 131072);           // 32768 B (expanded Ak)
    uint4*    sTokLo = (uint4*)(smem + 163840);           // 32768 B
    uint4*    sTokHi = (uint4*)(smem + 196608);           // 32768 B
    int*      sArX   = (int*)(smem + 229376);             // 72 ints
    uint32_t* sRed   = (uint32_t*)(smem + 229664);        // 32 warps x 9

    const int tid = threadIdx.x;
    const int lane = tid & 31, wid = tid >> 5;
    const int bx = (int)blockIdx.x;

    // ---------------- Phase A: distributed precompute -> global ------------
    // (1) token row packing + AkE/AqU: warp wid handles row bx + 152*wid
    {
        int row = bx + GRID_MAIN * wid;
        if (row < SEQ) {
            uint32_t w[8];
            #pragma unroll
            for (int q = 0; q < 8; q++) {
                int v = tokens[row * BITS + q * 32 + lane];
                w[q] = __ballot_sync(0xFFFFFFFFu, v & 1);
            }
            if (lane < 8) {
                g_tok[row * 8 + lane] = w[lane];
                int h = lane;
                uint32_t aq = 0, ak = 0, ar8 = 0;
                for (int k = 0; k < NBPN; k++) {
                    int idx = head_idx[h * NBPN + k];
                    if (idx < BITS) {
                        aq |= ((w[idx >> 5] >> (idx & 31)) & 1u) << k;
                    } else if (idx < 2 * BITS) {
                        int i2 = idx - BITS;
                        ak |= ((w[i2 >> 5] >> (i2 & 31)) & 1u) << k;
                    } else {
                        int p = idx - 2 * BITS;
                        if (p > 3) p = 3;
                        ar8 |= (uint32_t)((MAXD >> p) & 1) << k;
                    }
                }
                g_AkE[row * 8 + h] = (unsigned short)expand_idx(ak);
                g_AqU[row * 8 + h] = expand_idx(((uint32_t)h << 12) | aq | ar8);
            }
        }
        // (2) table bit-packing: warps 16..22 pack words bx*7 + (wid-16)
        if (wid >= 16 && wid < 23) {
            int word = bx * 7 + (wid - 16);
            if (word < HEADS * 128) {
                uint32_t wv = __ballot_sync(0xFFFFFFFFu,
                                            table[word * 32 + lane] > 0.5f);
                if (lane == 0) g_tabBits[word] = wv;
            }
        }
        // (3) ArX straight into this CTA's smem (local, no global round-trip)
        if (tid < (MAXD + 1) * HEADS) {
            int d = tid / HEADS, h = tid % HEADS;
            uint32_t ard = 0, ar8 = 0;
            for (int k = 0; k < NBPN; k++) {
                int idx = head_idx[h * NBPN + k];
                if (idx >= 2 * BITS) {
                    int p = idx - 2 * BITS;
                    if (p > 3) p = 3;
                    ard |= (uint32_t)((d    >> p) & 1) << k;
                    ar8 |= (uint32_t)((MAXD >> p) & 1) << k;
                }
            }
            sArX[tid] = (int)(expand_idx(ard) ^ expand_idx(ar8));
        }
    }

    // ---------------- global ticket barrier (monotonic across replays) -----
    __syncthreads();
    __threadfence();
    if (tid == 0) {
        unsigned int t = atomicAdd(&g_bar, 1u);
        unsigned int target = (t / GRID_MAIN + 1u) * GRID_MAIN;
        while (atomicAdd(&g_bar, 0u) < target) {
            __nanosleep(64);
        }
    }
    __syncthreads();

    // ---------------- Phase B: stage working set into SMEM -----------------
    {
        uint32_t val = g_tabBits[tid];
        uint32_t* sRep = (uint32_t*)smem;
        #pragma unroll
        for (int r = 0; r < 32; r++) {
            int L = (r + lane) & 31;                 // staggered, conflict-free
            sRep[tid * 32 + L] = val;
        }
        const uint4* g2 = (const uint4*)g_AkE;
        for (int x = tid; x < 2048; x += NT) sAk4[x] = g2[x];
        const uint4* g3 = (const uint4*)g_tok;
        for (int x = tid; x < 4096; x += NT) {
            uint4 v = g3[x];
            if (x & 1) sTokHi[x >> 1] = v; else sTokLo[x >> 1] = v;
        }
    }
    __syncthreads();

    const int pair = wid >> 1, sub = wid & 1;
    // SMSP balance: permute row-blocks so both SMSP groups carry equal work.
    const int pb = (pair >> 1) & 1;
    const int rowblk = pair + ((pair & 1) ? -pb : pb);   // bijection on 0..15
    const int i = rowblk * GRID_MAIN + ((rowblk & 1) ? (GRID_MAIN - 1 - bx) : bx);
    const bool active = (i < SEQ);

    uint32_t a[8] = {0, 0, 0, 0, 0, 0, 0, 0};
    int kmax = -1;
    const uint32_t laneOff = (uint32_t)lane << 2;

    if (active) {
        uint32_t u[8];
        {
            const uint4* gu = (const uint4*)(g_AqU + i * 8);
            uint4 u03 = gu[0], u47 = gu[1];
            u[0] = u03.x; u[1] = u03.y; u[2] = u03.z; u[3] = u03.w;
            u[4] = u47.x; u[5] = u47.y; u[6] = u47.z; u[7] = u47.w;
        }

        // main loop: j <= i-8 (rel part is exactly ar8; no fixups).
        int j = lane + 32 * sub;
        const int jend = i - MAXD;
        int jj = 2047 - j;
        if (j <= jend) {
            uint4 akv = sAk4[j];                      // primed
            #pragma unroll 2
            for (; j <= jend; j += 64, jj -= 64) {
                // prefetch next akv (clamped dummy read at the tail)
                uint4 akn = sAk4[min(j + 64, jend)];
                // token words: unconditional, independent of gather chain
                uint4 t0 = sTokLo[j];
                uint4 t1 = sTokHi[j];

                uint32_t A0 = u[0] + (akv.x & 0xFFFFu);
                uint32_t A1 = u[1] + (akv.x >> 16);
                uint32_t A2 = u[2] + (akv.y & 0xFFFFu);
                uint32_t A3 = u[3] + (akv.y >> 16);
                uint32_t A4 = u[4] + (akv.z & 0xFFFFu);
                uint32_t A5 = u[5] + (akv.z >> 16);
                uint32_t A6 = u[6] + (akv.w & 0xFFFFu);
                uint32_t A7 = u[7] + (akv.w >> 16);

                uint32_t w0 = *(const uint32_t*)(smem + ((A0 & 0xFFFFFF80u) | laneOff));
                uint32_t w1 = *(const uint32_t*)(smem + ((A1 & 0xFFFFFF80u) | laneOff));
                uint32_t w2 = *(const uint32_t*)(smem + ((A2 & 0xFFFFFF80u) | laneOff));
                uint32_t w3 = *(const uint32_t*)(smem + ((A3 & 0xFFFFFF80u) | laneOff));
                uint32_t w4 = *(const uint32_t*)(smem + ((A4 & 0xFFFFFF80u) | laneOff));
                uint32_t w5 = *(const uint32_t*)(smem + ((A5 & 0xFFFFFF80u) | laneOff));
                uint32_t w6 = *(const uint32_t*)(smem + ((A6 & 0xFFFFFF80u) | laneOff));
                uint32_t w7 = *(const uint32_t*)(smem + ((A7 & 0xFFFFFF80u) | laneOff));

                int v = (int)((w0 >> (A0 & 31u)) & 1u) + (int)((w1 >> (A1 & 31u)) & 1u)
                      + (int)((w2 >> (A2 & 31u)) & 1u) + (int)((w3 >> (A3 & 31u)) & 1u)
                      + (int)((w4 >> (A4 & 31u)) & 1u) + (int)((w5 >> (A5 & 31u)) & 1u)
                      + (int)((w6 >> (A6 & 31u)) & 1u) + (int)((w7 >> (A7 & 31u)) & 1u);

                // branchless: a ^= t & m is one LOP3 per word
                uint32_t m = (uint32_t)(-(int)(v >= HEADS / 2));
                a[0] ^= t0.x & m; a[1] ^= t0.y & m; a[2] ^= t0.z & m; a[3] ^= t0.w & m;
                a[4] ^= t1.x & m; a[5] ^= t1.y & m; a[6] ^= t1.z & m; a[7] ^= t1.w & m;

                kmax = max(kmax, v * 4096 + jj);   // IMAD + IMNMX (fma pipe)
                akv = akn;
            }
        }

        // diagonal tail: d = 0..7, lane d handles j = i-d (sub 0 warp only)
        if (sub == 0 && lane < MAXD && lane <= i) {
            int jt = i - lane;
            const unsigned short* s = (const unsigned short*)sAk4 + jt * 8;
            const int* ax = sArX + lane * 8;
            int v = 0;
            #pragma unroll
            for (int h = 0; h < 8; h++) {
                uint32_t A = (u[h] ^ (uint32_t)ax[h]) + (uint32_t)s[h];
                uint32_t w = *(const uint32_t*)(smem + ((A & 0xFFFFFF80u) | laneOff));
                v += (int)((w >> (A & 31u)) & 1u);
            }
            uint32_t m = (uint32_t)(-(int)(v >= HEADS / 2));
            uint4 t0 = sTokLo[jt];
            uint4 t1 = sTokHi[jt];
            a[0] ^= t0.x & m; a[1] ^= t0.y & m; a[2] ^= t0.z & m; a[3] ^= t0.w & m;
            a[4] ^= t1.x & m; a[5] ^= t1.y & m; a[6] ^= t1.z & m; a[7] ^= t1.w & m;
            kmax = max(kmax, v * 4096 + (2047 - jt));
        }

        // warp butterfly
        #pragma unroll
        for (int s = 16; s; s >>= 1) {
            #pragma unroll
            for (int q = 0; q < 8; q++)
                a[q] ^= __shfl_xor_sync(0xFFFFFFFFu, a[q], s);
            kmax = max(kmax, __shfl_xor_sync(0xFFFFFFFFu, kmax, s));
        }

        // odd warp parks its partial for its even partner
        if (sub == 1 && lane < 9) {
            uint32_t v = (lane < 8) ? a[lane] : (uint32_t)kmax;
            sRed[wid * 9 + lane] = v;
        }
    }

    __syncthreads();   // single block sync

    if (active && sub == 0) {
        const uint32_t* p = sRed + (wid + 1) * 9;
        #pragma unroll
        for (int q = 0; q < 8; q++) a[q] ^= p[q];
        kmax = max(kmax, (int)p[8]);

        int widx = lane >> 2;
        uint32_t w;
        if ((kmax >> 12) >= HEADS / 2) {          // any attended -> parity
            w = a[0];
            if (widx == 1) w = a[1];
            if (widx == 2) w = a[2];
            if (widx == 3) w = a[3];
            if (widx == 4) w = a[4];
            if (widx == 5) w = a[5];
            if (widx == 6) w = a[6];
            if (widx == 7) w = a[7];
        } else {                                   // fallback: argmax row
            int aj = 2047 - (kmax & 4095);
            const uint32_t* lo = (const uint32_t*)sTokLo;
            const uint32_t* hi = (const uint32_t*)sTokHi;
            w = (widx < 4) ? lo[aj * 4 + widx] : hi[aj * 4 + (widx - 4)];
        }
        int sh = (lane & 3) * 8;
        float4* o = (float4*)(out + i * BITS + lane * 8);
        o[0] = make_float4((float)((w >> (sh + 0)) & 1u), (float)((w >> (sh + 1)) & 1u),
                           (float)((w >> (sh + 2)) & 1u), (float)((w >> (sh + 3)) & 1u));
        o[1] = make_float4((float)((w >> (sh + 4)) & 1u), (float)((w >> (sh + 5)) & 1u),
                           (float)((w >> (sh + 6)) & 1u), (float)((w >> (sh + 7)) & 1u));
    }
}

extern "C" void kernel_launch(void* const* d_in, const int* in_sizes, int n_in,
                              void* d_out, int out_size) {
    const int*   tokens   = (const int*)d_in[0];
    const int*   head_idx = (const int*)d_in[1];
    const float* table    = (const float*)d_in[2];
    float*       out      = (float*)d_out;

    const int SMEM_BYTES = 229664 + 32 * 9 * 4;   // 230816 B
    cudaFuncSetAttribute(fused_kernel,
                         cudaFuncAttributeMaxDynamicSharedMemorySize, SMEM_BYTES);

    fused_kernel<<<GRID_MAIN, NT, SMEM_BYTES>>>(tokens, head_idx, table, out);
}